// round 9
// baseline (speedup 1.0000x reference)
#include <cuda_runtime.h>
#include <cuda_bf16.h>
#include <cstdint>
#include <math.h>

// Problem constants
#define Bb   2
#define Tt   2048
#define Dd   1024
#define Hh   16
#define DHd  64
#define Mrows (Bb*Tt)      // 4096
#define Gheads (Bb*Hh)     // 32
#define CHK  64
#define NCk  (Tt/CHK)      // 32
#define EPSv 1e-6f

// Scratch (device globals: allocation-free per harness rules)
__device__ float g_q[Gheads*Tt*DHd];
__device__ float g_k[Gheads*Tt*DHd];
__device__ float g_v[Gheads*Tt*DHd];
__device__ float g_state[Gheads*NCk*DHd*DHd];
__device__ float g_zsum[Gheads*NCk*DHd];

// bf16 hi/lo split buffers
__device__ __align__(16) __nv_bfloat16 g_xhi[Mrows*Dd];
__device__ __align__(16) __nv_bfloat16 g_xlo[Mrows*Dd];
__device__ __align__(16) __nv_bfloat16 g_whi[4*Dd*Dd];
__device__ __align__(16) __nv_bfloat16 g_wlo[4*Dd*Dd];
__device__ __align__(16) __nv_bfloat16 g_ahi[Mrows*Dd];
__device__ __align__(16) __nv_bfloat16 g_alo[Mrows*Dd];

// ===========================================================================
// helpers
// ===========================================================================
__device__ __forceinline__ uint32_t smem_to_u32(const void* p) {
    uint32_t a;
    asm("{ .reg .u64 t; cvta.to.shared.u64 t, %1; cvt.u32.u64 %0, t; }"
        : "=r"(a) : "l"(p));
    return a;
}

__device__ __forceinline__ void cp16(uint32_t saddr, const void* g) {
    asm volatile("cp.async.cg.shared.global [%0], [%1], 16;"
                 :: "r"(saddr), "l"(g));
}
#define CP_COMMIT() asm volatile("cp.async.commit_group;" ::: "memory")
#define CP_WAIT1()  asm volatile("cp.async.wait_group 1;" ::: "memory")

#define LDSM4(r, addr) \
    asm volatile("ldmatrix.sync.aligned.m8n8.x4.shared.b16 {%0,%1,%2,%3}, [%4];" \
                 : "=r"((r)[0]), "=r"((r)[1]), "=r"((r)[2]), "=r"((r)[3]) \
                 : "r"(addr))

__device__ __forceinline__ void mma16816(float* c, const uint32_t* a, const uint32_t* b) {
    asm volatile(
        "mma.sync.aligned.m16n8k16.row.col.f32.bf16.bf16.f32 "
        "{%0,%1,%2,%3}, {%4,%5,%6,%7}, {%8,%9}, {%0,%1,%2,%3};"
        : "+f"(c[0]), "+f"(c[1]), "+f"(c[2]), "+f"(c[3])
        : "r"(a[0]), "r"(a[1]), "r"(a[2]), "r"(a[3]), "r"(b[0]), "r"(b[1]));
}

// fp32 float4 -> packed hi/lo bf16 (4 each, as uint2)
__device__ __forceinline__ void split_bf16x4(float4 a, uint2& hi, uint2& lo)
{
    __nv_bfloat16 h0 = __float2bfloat16(a.x);
    __nv_bfloat16 h1 = __float2bfloat16(a.y);
    __nv_bfloat16 h2 = __float2bfloat16(a.z);
    __nv_bfloat16 h3 = __float2bfloat16(a.w);
    __nv_bfloat16 l0 = __float2bfloat16(a.x - __bfloat162float(h0));
    __nv_bfloat16 l1 = __float2bfloat16(a.y - __bfloat162float(h1));
    __nv_bfloat16 l2 = __float2bfloat16(a.z - __bfloat162float(h2));
    __nv_bfloat16 l3 = __float2bfloat16(a.w - __bfloat162float(h3));
    hi.x = (uint32_t)__bfloat16_as_ushort(h0) | ((uint32_t)__bfloat16_as_ushort(h1) << 16);
    hi.y = (uint32_t)__bfloat16_as_ushort(h2) | ((uint32_t)__bfloat16_as_ushort(h3) << 16);
    lo.x = (uint32_t)__bfloat16_as_ushort(l0) | ((uint32_t)__bfloat16_as_ushort(l1) << 16);
    lo.y = (uint32_t)__bfloat16_as_ushort(l2) | ((uint32_t)__bfloat16_as_ushort(l3) << 16);
}

// ===========================================================================
// split kernels: fp32 -> bf16 hi/lo
// ===========================================================================
__global__ void split_x_kernel(const float4* __restrict__ src,
                               uint2* __restrict__ hi, uint2* __restrict__ lo, int n4)
{
    int i = blockIdx.x * blockDim.x + threadIdx.x;
    if (i >= n4) return;
    float4 v = __ldg(&src[i]);
    uint2 h, l;
    split_bf16x4(v, h, l);
    hi[i] = h;
    lo[i] = l;
}

// all 4 weight matrices in one launch; quarter = i >> 18 (Dd*Dd/4 = 2^18)
__global__ void split_w_kernel(const float4* __restrict__ w0,
                               const float4* __restrict__ w1,
                               const float4* __restrict__ w2,
                               const float4* __restrict__ w3,
                               uint2* __restrict__ hi, uint2* __restrict__ lo)
{
    int i = blockIdx.x * blockDim.x + threadIdx.x;
    const int quarter = i >> 18;
    const int r = i & ((1 << 18) - 1);
    const float4* src = (quarter == 0) ? w0 : (quarter == 1) ? w1
                       : (quarter == 2) ? w2 : w3;
    float4 v = __ldg(&src[r]);
    uint2 h, l;
    split_bf16x4(v, h, l);
    hi[i] = h;
    lo[i] = l;
}

// Keeps the QKV GEMM in the ncu capture slot (#4).
__global__ void nop_kernel() {}

// ===========================================================================
// Tensor-core GEMM via mma.sync (bf16x3 split):
// C[M=4096,N=1024] = A[M,K=1024] @ W[N,K]^T + bias
// CTA tile 128x256, warp tile 64x64, BK=32, 3-stage cp.async.
// Inner loop: per ks, ALL 16 fragment LDSMs issue before any MMA
// (latency-pipelined), then 96 uninterrupted HMMAs in 3 product passes.
// ===========================================================================
#define BKc   32                 // bf16 K per chunk
#define NCH   (Dd/BKc)           // 32
#define SSTR  40                 // smem row stride (bf16): 32 data + 8 pad
#define A_SMB (128*SSTR*2)       // 10240 B
#define W_SMB (256*SSTR*2)       // 20480 B
#define STAGE_SMB (2*A_SMB + 2*W_SMB)  // 61440 B
#define NSTAGE 3
#define SMEM_GEMM (NSTAGE*STAGE_SMB)   // 184320 B

__global__ __launch_bounds__(256, 1)
void mma_gemm_kernel(const __nv_bfloat16* __restrict__ Ahi,
                     const __nv_bfloat16* __restrict__ Alo,
                     const __nv_bfloat16* __restrict__ WhiB,
                     const __nv_bfloat16* __restrict__ WloB,
                     const float* __restrict__ b0,
                     const float* __restrict__ b1,
                     const float* __restrict__ b2,
                     float* __restrict__ d0,
                     float* __restrict__ d1,
                     float* __restrict__ d2,
                     int mode)
{
    extern __shared__ char smem[];
    const uint32_t sb = smem_to_u32(smem);
    const int tid  = threadIdx.x;
    const int lane = tid & 31, wid = tid >> 5;
    const int m0 = blockIdx.x * 128, n0 = blockIdx.y * 256;
    const int z  = blockIdx.z;

    const __nv_bfloat16* Whi = WhiB + (size_t)z * Dd * Dd;
    const __nv_bfloat16* Wlo = WloB + (size_t)z * Dd * Dd;
    const float* bias = (z == 0) ? b0 : (z == 1) ? b1 : b2;
    float* dst        = (z == 0) ? d0 : (z == 1) ? d1 : d2;
    const bool do_elu = (mode == 0) && (z < 2);

    // ---- loader mapping: 4 groups x 64 threads ----
    const int grp = tid >> 6;
    const int lt  = tid & 63;
    const __nv_bfloat16* gtile;
    uint32_t toff;
    if      (grp == 0) { gtile = Ahi + (size_t)m0 * Dd; toff = 0; }
    else if (grp == 1) { gtile = Alo + (size_t)m0 * Dd; toff = A_SMB; }
    else if (grp == 2) { gtile = Whi + (size_t)n0 * Dd; toff = 2*A_SMB; }
    else               { gtile = Wlo + (size_t)n0 * Dd; toff = 2*A_SMB + W_SMB; }
    const bool isW = (grp >= 2);

    float acc[4][8][4];
    #pragma unroll
    for (int a = 0; a < 4; a++)
        #pragma unroll
        for (int b = 0; b < 8; b++)
            #pragma unroll
            for (int c = 0; c < 4; c++) acc[a][b][c] = 0.f;

    // issue loads of chunk kc into stage kc%NSTAGE
    auto issue = [&](int kc) {
        const uint32_t stb = sb + (kc % NSTAGE) * STAGE_SMB + toff;
        const __nv_bfloat16* g = gtile + kc * BKc;
        #pragma unroll
        for (int j = 0; j < 16; j++) {
            if (j < 8 || isW) {
                int chunk = lt + j * 64;       // A: 0..511, W: 0..1023
                int row = chunk >> 2;
                int c8  = (chunk & 3) * 8;
                cp16(stb + (uint32_t)(row * SSTR + c8) * 2,
                     g + (size_t)row * Dd + c8);
            }
        }
    };

    issue(0); CP_COMMIT();
    issue(1); CP_COMMIT();

    // warp layout: 2 (M) x 4 (N); warp tile 64x64
    const int wm = (wid & 1) * 64;
    const int wn = (wid >> 1) * 64;
    const int arow = (lane & 7) + ((lane >> 3) & 1) * 8;
    const int acol = ((lane >> 4) & 1) * 8;
    const int brow = (lane & 7) + ((lane >> 4) & 1) * 8;
    const int bcol = ((lane >> 3) & 1) * 8;

    for (int kc = 0; kc < NCH; kc++) {
        CP_WAIT1();
        __syncthreads();
        if (kc + 2 < NCH) { issue(kc + 2); CP_COMMIT(); }

        const uint32_t stb = sb + (kc % NSTAGE) * STAGE_SMB;
        const uint32_t aH = stb;
        const uint32_t aL = stb + A_SMB;
        const uint32_t wH = stb + 2 * A_SMB;
        const uint32_t wL = stb + 2 * A_SMB + W_SMB;

        #pragma unroll
        for (int ks = 0; ks < 2; ks++) {
            // ---- phase 1: ALL fragment loads (16 LDSM.x4) ----
            uint32_t ah[4][4], al[4][4], bh[4][4], bl[4][4];
            #pragma unroll
            for (int mi = 0; mi < 4; mi++) {
                uint32_t off = (uint32_t)((wm + mi * 16 + arow) * SSTR + ks * 16 + acol) * 2;
                LDSM4(ah[mi], aH + off);
                LDSM4(al[mi], aL + off);
            }
            #pragma unroll
            for (int nj = 0; nj < 4; nj++) {
                uint32_t off = (uint32_t)((wn + nj * 16 + brow) * SSTR + ks * 16 + bcol) * 2;
                LDSM4(bh[nj], wH + off);
                LDSM4(bl[nj], wL + off);
            }
            // ---- phase 2: 96 uninterrupted MMAs (3 product passes) ----
            #pragma unroll
            for (int nj = 0; nj < 4; nj++)
                #pragma unroll
                for (int mi = 0; mi < 4; mi++)
                    #pragma unroll
                    for (int hf = 0; hf < 2; hf++)
                        mma16816(acc[mi][nj * 2 + hf], ah[mi], &bh[nj][hf * 2]);
            #pragma unroll
            for (int nj = 0; nj < 4; nj++)
                #pragma unroll
                for (int mi = 0; mi < 4; mi++)
                    #pragma unroll
                    for (int hf = 0; hf < 2; hf++)
                        mma16816(acc[mi][nj * 2 + hf], ah[mi], &bl[nj][hf * 2]);
            #pragma unroll
            for (int nj = 0; nj < 4; nj++)
                #pragma unroll
                for (int mi = 0; mi < 4; mi++)
                    #pragma unroll
                    for (int hf = 0; hf < 2; hf++)
                        mma16816(acc[mi][nj * 2 + hf], al[mi], &bh[nj][hf * 2]);
        }
    }

    // ---- epilogue ----
    const int gid = lane >> 2, qid = lane & 3;
    float bv[16];
    #pragma unroll
    for (int ni = 0; ni < 8; ni++) {
        int n = n0 + wn + ni * 8 + qid * 2;
        bv[2 * ni]     = __ldg(&bias[n]);
        bv[2 * ni + 1] = __ldg(&bias[n + 1]);
    }

    #pragma unroll
    for (int mi = 0; mi < 4; mi++) {
        #pragma unroll
        for (int rr = 0; rr < 2; rr++) {
            const int m = m0 + wm + mi * 16 + gid + rr * 8;
            #pragma unroll
            for (int ni = 0; ni < 8; ni++) {
                const int n = n0 + wn + ni * 8 + qid * 2;
                float v0 = acc[mi][ni][rr * 2 + 0] + bv[2 * ni];
                float v1 = acc[mi][ni][rr * 2 + 1] + bv[2 * ni + 1];
                if (do_elu) {
                    v0 = (v0 > 0.f) ? (v0 + 1.f) : __expf(v0);
                    v1 = (v1 > 0.f) ? (v1 + 1.f) : __expf(v1);
                }
                if (mode == 2) {
                    *(float2*)&dst[(size_t)m * Dd + n] = make_float2(v0, v1);
                } else {
                    const int h = n >> 6, dh = n & 63;
                    const int b = m >> 11, t = m & (Tt - 1);
                    *(float2*)&dst[((size_t)(b * Hh + h) * Tt + t) * DHd + dh] =
                        make_float2(v0, v1);
                }
            }
        }
    }
}

// ---------------------------------------------------------------------------
// Pass 1: per-chunk local stats  KtV[d][e] = sum_i K[i][d]*V[i][e], ksum[d]
// ---------------------------------------------------------------------------
__global__ __launch_bounds__(128)
void chunk_stats_kernel()
{
    __shared__ float sK[CHK * DHd];
    __shared__ float sV[CHK * DHd];
    const int g = blockIdx.x, c = blockIdx.y;
    const int tid = threadIdx.x;
    const float* Kg = g_k + ((size_t)g * Tt + c * CHK) * DHd;
    const float* Vg = g_v + ((size_t)g * Tt + c * CHK) * DHd;

    for (int i = tid; i < CHK * DHd / 4; i += 128) {
        ((float4*)sK)[i] = ((const float4*)Kg)[i];
        ((float4*)sV)[i] = ((const float4*)Vg)[i];
    }
    __syncthreads();

    const int tx = tid & 15, ty = tid >> 4;   // 16 x 8
    const int d0 = ty * 8, e0 = tx * 4;
    float acc[8][4];
    #pragma unroll
    for (int u = 0; u < 8; u++)
        #pragma unroll
        for (int v = 0; v < 4; v++) acc[u][v] = 0.f;

    for (int i = 0; i < CHK; i++) {
        float a[8], b[4];
        *(float4*)(a)     = *(const float4*)&sK[i * DHd + d0];
        *(float4*)(a + 4) = *(const float4*)&sK[i * DHd + d0 + 4];
        *(float4*)(b)     = *(const float4*)&sV[i * DHd + e0];
        #pragma unroll
        for (int u = 0; u < 8; u++)
            #pragma unroll
            for (int v = 0; v < 4; v++)
                acc[u][v] = fmaf(a[u], b[v], acc[u][v]);
    }

    float* outp = g_state + ((size_t)g * NCk + c) * DHd * DHd;
    #pragma unroll
    for (int u = 0; u < 8; u++)
        *(float4*)&outp[(d0 + u) * DHd + e0] =
            make_float4(acc[u][0], acc[u][1], acc[u][2], acc[u][3]);

    if (tid < DHd) {
        float s = 0.f;
        for (int i = 0; i < CHK; i++) s += sK[i * DHd + tid];
        g_zsum[((size_t)g * NCk + c) * DHd + tid] = s;
    }
}

// ---------------------------------------------------------------------------
// Pass 2: exclusive prefix over chunks (batched loads -> register scan)
// ---------------------------------------------------------------------------
__global__ void scan_state_kernel()
{
    const int g = blockIdx.x;
    const int j = blockIdx.y * 256 + threadIdx.x;   // < 4096
    float* base = g_state + (size_t)g * NCk * DHd * DHd + j;
    float r[NCk];
    #pragma unroll
    for (int c = 0; c < NCk; c++) r[c] = base[(size_t)c * DHd * DHd];
    float run = 0.f;
    #pragma unroll
    for (int c = 0; c < NCk; c++) {
        base[(size_t)c * DHd * DHd] = run;
        run += r[c];
    }
}

__global__ void scan_z_kernel()
{
    const int g = blockIdx.x;
    const int j = threadIdx.x;  // < 64
    float* base = g_zsum + (size_t)g * NCk * DHd + j;
    float r[NCk];
    #pragma unroll
    for (int c = 0; c < NCk; c++) r[c] = base[c * DHd];
    float run = 0.f;
    #pragma unroll
    for (int c = 0; c < NCk; c++) {
        base[c * DHd] = run;
        run += r[c];
    }
}

// ---------------------------------------------------------------------------
// Pass 3: per-chunk output.  out = (maskedA@V + Q@S) / max(denom, eps)
// Writes bf16 hi/lo split directly (feeds final GEMM).
// ---------------------------------------------------------------------------
__global__ __launch_bounds__(256)
void attn_out_kernel()
{
    extern __shared__ float sm[];
    float* sQ   = sm;            // 4096 (pitch 64)
    float* sKV  = sQ + 4096;     // 4160 (K pitch 65, then V pitch 64)
    float* sS   = sKV + 4160;    // 4096 (pitch 64)
    float* sA   = sS + 4096;     // 4096 (pitch 64)
    float* zrun = sA + 4096;     // 64
    float* sden = zrun + 64;     // 64

    const int g = blockIdx.x, c = blockIdx.y;
    const int tid = threadIdx.x;
    const float* Qg = g_q + ((size_t)g * Tt + c * CHK) * DHd;
    const float* Kg = g_k + ((size_t)g * Tt + c * CHK) * DHd;
    const float* Vg = g_v + ((size_t)g * Tt + c * CHK) * DHd;
    const float* Sg = g_state + ((size_t)g * NCk + c) * DHd * DHd;

    for (int i = tid; i < 1024; i += 256) {
        ((float4*)sQ)[i] = ((const float4*)Qg)[i];
        ((float4*)sS)[i] = ((const float4*)Sg)[i];
        float4 kv = ((const float4*)Kg)[i];
        int j = i * 4;
        int r = j >> 6, col = j & 63;
        float* p = sKV + r * 65 + col;
        p[0] = kv.x; p[1] = kv.y; p[2] = kv.z; p[3] = kv.w;
    }
    if (tid < DHd) zrun[tid] = g_zsum[((size_t)g * NCk + c) * DHd + tid];
    __syncthreads();

    const int tx = tid & 15, ty = tid >> 4;
    const int i0 = ty * 4, j0 = tx * 4;

    // A = (Q K^T) masked causal (inclusive)
    {
        float acc[4][4];
        #pragma unroll
        for (int u = 0; u < 4; u++)
            #pragma unroll
            for (int v = 0; v < 4; v++) acc[u][v] = 0.f;
        for (int d = 0; d < DHd; d++) {
            float a[4], b[4];
            #pragma unroll
            for (int u = 0; u < 4; u++) a[u] = sQ[(i0 + u) * 64 + d];
            #pragma unroll
            for (int v = 0; v < 4; v++) b[v] = sKV[(j0 + v) * 65 + d];
            #pragma unroll
            for (int u = 0; u < 4; u++)
                #pragma unroll
                for (int v = 0; v < 4; v++)
                    acc[u][v] = fmaf(a[u], b[v], acc[u][v]);
        }
        #pragma unroll
        for (int u = 0; u < 4; u++)
            #pragma unroll
            for (int v = 0; v < 4; v++)
                sA[(i0 + u) * 64 + j0 + v] = (j0 + v <= i0 + u) ? acc[u][v] : 0.f;
    }
    __syncthreads();

    for (int i = tid; i < 1024; i += 256)
        ((float4*)sKV)[i] = ((const float4*)Vg)[i];
    if (tid < CHK) {
        float s = 0.f;
        for (int j = 0; j < CHK; j++) s += sA[tid * 64 + j];
        for (int d = 0; d < DHd; d++) s = fmaf(sQ[tid * 64 + d], zrun[d], s);
        sden[tid] = fmaxf(s, EPSv);
    }
    __syncthreads();

    {
        const int e0 = j0;
        float acc[4][4];
        #pragma unroll
        for (int u = 0; u < 4; u++)
            #pragma unroll
            for (int v = 0; v < 4; v++) acc[u][v] = 0.f;

        for (int j = 0; j < CHK; j++) {
            float4 b4 = *(const float4*)&sKV[j * 64 + e0];
            float b[4] = {b4.x, b4.y, b4.z, b4.w};
            float a[4];
            #pragma unroll
            for (int u = 0; u < 4; u++) a[u] = sA[(i0 + u) * 64 + j];
            #pragma unroll
            for (int u = 0; u < 4; u++)
                #pragma unroll
                for (int v = 0; v < 4; v++)
                    acc[u][v] = fmaf(a[u], b[v], acc[u][v]);
        }
        for (int d = 0; d < DHd; d++) {
            float4 b4 = *(const float4*)&sS[d * 64 + e0];
            float b[4] = {b4.x, b4.y, b4.z, b4.w};
            float a[4];
            #pragma unroll
            for (int u = 0; u < 4; u++) a[u] = sQ[(i0 + u) * 64 + d];
            #pragma unroll
            for (int u = 0; u < 4; u++)
                #pragma unroll
                for (int v = 0; v < 4; v++)
                    acc[u][v] = fmaf(a[u], b[v], acc[u][v]);
        }

        const int b = g / Hh, h = g % Hh;
        #pragma unroll
        for (int u = 0; u < 4; u++) {
            int t = c * CHK + i0 + u;
            float inv = 1.f / sden[i0 + u];
            float4 o = make_float4(acc[u][0] * inv, acc[u][1] * inv,
                                   acc[u][2] * inv, acc[u][3] * inv);
            size_t idx = ((size_t)(b * Tt + t) * Hh + h) * DHd + e0;
            uint2 hi, lo;
            split_bf16x4(o, hi, lo);
            *(uint2*)&g_ahi[idx] = hi;
            *(uint2*)&g_alo[idx] = lo;
        }
    }
}

// ---------------------------------------------------------------------------
extern "C" void kernel_launch(void* const* d_in, const int* in_sizes, int n_in,
                              void* d_out, int out_size)
{
    const float* x  = (const float*)d_in[0];
    const float* Wq = (const float*)d_in[1];
    const float* bq = (const float*)d_in[2];
    const float* Wk = (const float*)d_in[3];
    const float* bk = (const float*)d_in[4];
    const float* Wv = (const float*)d_in[5];
    const float* bv = (const float*)d_in[6];
    const float* Wo = (const float*)d_in[7];
    const float* bo = (const float*)d_in[8];
    float* out = (float*)d_out;

    float *pq, *pk, *pv;
    __nv_bfloat16 *pxhi, *pxlo, *pwhi, *pwlo, *pahi, *palo;
    cudaGetSymbolAddress((void**)&pq,   g_q);
    cudaGetSymbolAddress((void**)&pk,   g_k);
    cudaGetSymbolAddress((void**)&pv,   g_v);
    cudaGetSymbolAddress((void**)&pxhi, g_xhi);
    cudaGetSymbolAddress((void**)&pxlo, g_xlo);
    cudaGetSymbolAddress((void**)&pwhi, g_whi);
    cudaGetSymbolAddress((void**)&pwlo, g_wlo);
    cudaGetSymbolAddress((void**)&pahi, g_ahi);
    cudaGetSymbolAddress((void**)&palo, g_alo);

    static int attr_done = 0;
    if (!attr_done) {
        cudaFuncSetAttribute(mma_gemm_kernel,
                             cudaFuncAttributeMaxDynamicSharedMemorySize, SMEM_GEMM);
        cudaFuncSetAttribute(attn_out_kernel,
                             cudaFuncAttributeMaxDynamicSharedMemorySize,
                             (4096 + 4160 + 4096 + 4096 + 64 + 64) * (int)sizeof(float));
        attr_done = 1;
    }
    const int smem3 = (4096 + 4160 + 4096 + 4096 + 64 + 64) * sizeof(float);

    // --- split fp32 -> bf16 hi/lo ---
    const int xN4 = Mrows * Dd / 4;       // 1M
    const int wN4 = Dd * Dd / 4;          // 256K per matrix
    split_x_kernel<<<(xN4 + 255) / 256, 256>>>((const float4*)x,
        (uint2*)pxhi, (uint2*)pxlo, xN4);
    split_w_kernel<<<(4 * wN4) / 256, 256>>>(
        (const float4*)Wq, (const float4*)Wk, (const float4*)Wv, (const float4*)Wo,
        (uint2*)pwhi, (uint2*)pwlo);

    // keep QKV GEMM in ncu capture slot (#4)
    nop_kernel<<<1, 32>>>();

    // --- Q/K/V projections in one batched launch (tensor cores) ---
    dim3 gQKV(Mrows / 128, Dd / 256, 3);   // (32, 4, 3)
    mma_gemm_kernel<<<gQKV, 256, SMEM_GEMM>>>(pxhi, pxlo, pwhi, pwlo,
        bq, bk, bv, pq, pk, pv, 0);

    // --- linear attention ---
    chunk_stats_kernel<<<dim3(Gheads, NCk), 128>>>();
    scan_state_kernel<<<dim3(Gheads, DHd * DHd / 256), 256>>>();
    scan_z_kernel<<<Gheads, DHd>>>();
    attn_out_kernel<<<dim3(Gheads, NCk), 256, smem3>>>();

    // --- output projection ---
    dim3 gOut(Mrows / 128, Dd / 256, 1);
    mma_gemm_kernel<<<gOut, 256, SMEM_GEMM>>>(pahi, palo,
        pwhi + 3 * (size_t)Dd * Dd, pwlo + 3 * (size_t)Dd * Dd,
        bo, bo, bo, out, out, out, 2);
}